// round 7
// baseline (speedup 1.0000x reference)
#include <cuda_runtime.h>

// SNN: B=1024, T=4096, 6 -> 10 -> 27 LIF (subtract reset). One warp per batch.
// Pipelined 8-step sub-batches, all phases batched so NO instruction inside a
// recurrence run waits on LDS/VOTE/predicate:
//   (1) c1 LDS x8   (2) table fetch x8 (masks 8-15 steps old)
//   (3) L1 recurrence x8, spike values recorded to sf[]
//   (4) ballot burst x8 on sf[] (pred latency pipelines; sinks)
//   (5) L2 recurrence x8 (currents fetched last sub-batch, register-resident)

#define T_LEN 4096
#define NB 1024
#define BETA 0.9f
#define WARPS_PER_CTA 8
#define CTA_THREADS (WARPS_PER_CTA * 32)
#define N_CTAS (NB / WARPS_PER_CTA) /* 128 */
#define NCHUNK (T_LEN / 32)         /* 128 */

#define ZERO_ROW 1024u                     /* table row of zeros (pad region) */
#define TABLE_FLOATS (1024 * 27 + 32)
#define CURBUF_STRIDE 34                   /* even: aligned 64-bit stores */
#define CURBUF_FLOATS (32 * CURBUF_STRIDE)
#define CURBUF_PER_WARP (2 * CURBUF_FLOATS)
#define SMEM_FLOATS (TABLE_FLOATS + WARPS_PER_CTA * CURBUF_PER_WARP)
#define SMEM_BYTES (SMEM_FLOATS * 4) /* 180,352 B */

typedef unsigned long long u64;

__device__ __forceinline__ u64 pack2(float lo, float hi) {
    u64 r; asm("mov.b64 %0,{%1,%2};" : "=l"(r) : "f"(lo), "f"(hi)); return r;
}
__device__ __forceinline__ u64 mul2(u64 a, u64 b) {
    u64 r; asm("mul.rn.f32x2 %0,%1,%2;" : "=l"(r) : "l"(a), "l"(b)); return r;
}
__device__ __forceinline__ u64 fma2(u64 a, u64 b, u64 c) {
    u64 r; asm("fma.rn.f32x2 %0,%1,%2,%3;" : "=l"(r) : "l"(a), "l"(b), "l"(c)); return r;
}
__device__ __forceinline__ u64 add2(u64 a, u64 b) {
    u64 r; asm("add.rn.f32x2 %0,%1,%2;" : "=l"(r) : "l"(a), "l"(b)); return r;
}

// Phase A: 10 neuron currents for this lane's timestep, f32x2-packed.
// Per-half rounding == scalar ops; ascending-k order matches cublas.
__device__ __forceinline__ void phaseA_store(const float xv[6],
                                             const u64 w12r[5][6],
                                             const u64 b12r[5],
                                             float* wb, int lane)
{
    u64 xx[6];
#pragma unroll
    for (int c = 0; c < 6; c++) xx[c] = pack2(xv[c], xv[c]);
#pragma unroll
    for (int np = 0; np < 5; np++) {
        u64 a = mul2(xx[0], w12r[np][0]);
#pragma unroll
        for (int c = 1; c < 6; c++)
            a = fma2(xx[c], w12r[np][c], a);
        a = add2(a, b12r[np]);
        *reinterpret_cast<u64*>(&wb[lane * CURBUF_STRIDE + 2 * np]) = a;
    }
}

// One chunk = 4 sub-batches of 8 steps; parity p alternates (4 subs/chunk ->
// chunk-invariant), carrying the pipeline state across chunks.
__device__ __forceinline__ void fused_chunk(const float* rb, int lane,
                                            const float* trow,
                                            float& m1, float& s1,
                                            float& m2, float& s2,
                                            unsigned (&msk)[2][8],
                                            float (&c2f)[2][8])
{
#pragma unroll
    for (int sb = 0; sb < 4; sb++) {
        const int p = sb & 1, q = p ^ 1;

        // (1) c1 loads for these 8 steps
        float c1r[8];
#pragma unroll
        for (int i = 0; i < 8; i++)
            c1r[i] = rb[(sb * 8 + i) * CURBUF_STRIDE + lane];

        // (2) table fetch for previous sub-batch's masks (VOTE long drained);
        //     results consumed only next sub-batch (LDS long drained).
#pragma unroll
        for (int i = 0; i < 8; i++)
            c2f[p][i] = trow[msk[q][i] * 27u];

        // (3) layer-1 recurrence, 8 steps; spikes recorded as floats.
        //     reference: mem = fma(beta,mem,cur) - rst ; rst in {0,1} exact.
        float sf[8];
#pragma unroll
        for (int i = 0; i < 8; i++) {
            float a1 = fmaf(BETA, m1, c1r[i]);
            m1 = __fsub_rn(a1, s1);
            s1 = (m1 > 1.0f) ? 1.0f : 0.0f;
            sf[i] = s1;
        }

        // (4) ballot burst: 8 independent FSETP+VOTE pairs, all sinks.
#pragma unroll
        for (int i = 0; i < 8; i++)
            msk[p][i] = __ballot_sync(0xffffffffu, sf[i] != 0.0f);

        // (5) layer-2 recurrence, 8 steps (register-resident currents).
#pragma unroll
        for (int i = 0; i < 8; i++) {
            float a2 = fmaf(BETA, m2, c2f[q][i]);
            m2 = __fsub_rn(a2, s2);
            s2 = (m2 > 1.0f) ? 1.0f : 0.0f;
        }
    }
}

__global__ void __launch_bounds__(CTA_THREADS, 1)
snn_kernel(const float* __restrict__ x, const float* __restrict__ W1,
           const float* __restrict__ b1, const float* __restrict__ W2,
           const float* __restrict__ b2, float* __restrict__ out)
{
    extern __shared__ float smem[];
    float* table  = smem;                 // [1024][27] + 32 zero pad (ZERO_ROW)
    float* curall = smem + TABLE_FLOATS;  // [WARPS][2][32][34]

    const int tid  = threadIdx.x;
    const int warp = tid >> 5;
    const int lane = tid & 31;
    const int b = blockIdx.x * WARPS_PER_CTA + warp;
    const float* xb = x + (size_t)b * (6 * T_LEN);

    float xv[6];
#pragma unroll
    for (int c = 0; c < 6; c++) xv[c] = xb[c * T_LEN + lane];

    // Layer-2 lookup table: ascending-n accumulation == reference fma-dot
    // with 0/1 spikes (adding 0.0f is exact).
    for (int e = tid; e < 1024 * 27; e += CTA_THREADS) {
        int v = e / 27;
        int m = e - v * 27;
        float acc = 0.0f;
#pragma unroll
        for (int n = 0; n < 10; n++)
            if (v & (1 << n)) acc = __fadd_rn(acc, W2[m * 10 + n]);
        table[e] = __fadd_rn(acc, b2[m]);
    }
    for (int i = 1024 * 27 + tid; i < TABLE_FLOATS; i += CTA_THREADS)
        table[i] = 0.0f;  // ZERO_ROW lives here
    // staging columns 10..31 stay zero forever -> lanes 10..31 never spike
    for (int i = tid; i < WARPS_PER_CTA * CURBUF_PER_WARP; i += CTA_THREADS)
        curall[i] = 0.0f;
    __syncthreads();

    u64 w12r[5][6], b12r[5];
#pragma unroll
    for (int np = 0; np < 5; np++) {
        b12r[np] = pack2(b1[2 * np], b1[2 * np + 1]);
#pragma unroll
        for (int c = 0; c < 6; c++)
            w12r[np][c] = pack2(W1[(2 * np) * 6 + c], W1[(2 * np + 1) * 6 + c]);
    }

    float* cbuf  = curall + warp * CURBUF_PER_WARP;
    float* bank0 = cbuf;
    float* bank1 = cbuf + CURBUF_FLOATS;
    const float* trow = table + lane;

    float m1 = 0.0f, m2 = 0.0f, s1 = 0.0f, s2 = 0.0f;
    unsigned msk[2][8];
    float c2f[2][8];
#pragma unroll
    for (int i = 0; i < 8; i++) {
        msk[0][i] = ZERO_ROW; msk[1][i] = ZERO_ROW; // -> zero pad row
        c2f[0][i] = 0.0f;     c2f[1][i] = 0.0f;     // fake steps keep m2 == 0
    }

    // Prologue: phaseA(ch0)->bank0; xv <- ch1.
    phaseA_store(xv, w12r, b12r, bank0, lane);
#pragma unroll
    for (int c = 0; c < 6; c++) xv[c] = xb[c * T_LEN + 32 + lane];
    __syncwarp();

    // Chunks 0..125 in pairs.
#pragma unroll 1
    for (int k = 0; k < 126; k += 2) {
        // even chunk k: read bank0; phaseA(k+1)->bank1; prefetch x(k+2)
        float xn[6];
#pragma unroll
        for (int c = 0; c < 6; c++)
            xn[c] = xb[c * T_LEN + (k + 2) * 32 + lane];
        phaseA_store(xv, w12r, b12r, bank1, lane);
        fused_chunk(bank0, lane, trow, m1, s1, m2, s2, msk, c2f);
#pragma unroll
        for (int c = 0; c < 6; c++) xv[c] = xn[c];
        __syncwarp();

        // odd chunk k+1: read bank1; phaseA(k+2)->bank0; prefetch x(k+3)
#pragma unroll
        for (int c = 0; c < 6; c++)
            xn[c] = xb[c * T_LEN + (k + 3) * 32 + lane];
        phaseA_store(xv, w12r, b12r, bank0, lane);
        fused_chunk(bank1, lane, trow, m1, s1, m2, s2, msk, c2f);
#pragma unroll
        for (int c = 0; c < 6; c++) xv[c] = xn[c];
        __syncwarp();
    }

    // chunk 126: read bank0; phaseA(127)->bank1
    phaseA_store(xv, w12r, b12r, bank1, lane);
    fused_chunk(bank0, lane, trow, m1, s1, m2, s2, msk, c2f);
    __syncwarp();
    // chunk 127: read bank1
    fused_chunk(bank1, lane, trow, m1, s1, m2, s2, msk, c2f);

    // Epilogue: L2 lags by 16 steps. Last sub-batch had parity 1:
    // consume c2f[1] (fetched during the final sub-batch), then fetch+consume
    // the final sub-batch's own masks.
#pragma unroll
    for (int i = 0; i < 8; i++) {
        float a2 = fmaf(BETA, m2, c2f[1][i]);
        m2 = __fsub_rn(a2, s2);
        s2 = (m2 > 1.0f) ? 1.0f : 0.0f;
    }
#pragma unroll
    for (int i = 0; i < 8; i++) {
        float c = trow[msk[1][i] * 27u];
        float a2 = fmaf(BETA, m2, c);
        m2 = __fsub_rn(a2, s2);
        s2 = (m2 > 1.0f) ? 1.0f : 0.0f;
    }

    if (lane < 27)
        out[b * 27 + lane] = s2;
}

extern "C" void kernel_launch(void* const* d_in, const int* in_sizes, int n_in,
                              void* d_out, int out_size)
{
    const float* x  = (const float*)d_in[0];
    const float* W1 = (const float*)d_in[1];
    const float* b1 = (const float*)d_in[2];
    const float* W2 = (const float*)d_in[3];
    const float* b2 = (const float*)d_in[4];
    float* out = (float*)d_out;

    cudaFuncSetAttribute(snn_kernel, cudaFuncAttributeMaxDynamicSharedMemorySize,
                         SMEM_BYTES);

    snn_kernel<<<N_CTAS, CTA_THREADS, SMEM_BYTES>>>(x, W1, b1, W2, b2, out);
}

// round 8
// speedup vs baseline: 1.1936x; 1.1936x over previous
#include <cuda_runtime.h>

// SNN: B=1024, T=4096, 6 -> 10 -> 27 LIF (subtract reset). One warp per batch.
// Interleaved per-step body (R6) with both serializers removed:
//  - spike state via FSET (set.gt.f32.f32 -> 1.0f/0.0f), no predicate on chain
//  - ballot lagged one step (pred >=14cyc old -> no in-order issue stall)
//  - table fetch uses masks one sub-batch old; L2 lags L1 by 17 steps.

#define T_LEN 4096
#define NB 1024
#define BETA 0.9f
#define WARPS_PER_CTA 8
#define CTA_THREADS (WARPS_PER_CTA * 32)
#define N_CTAS (NB / WARPS_PER_CTA) /* 128 */
#define NCHUNK (T_LEN / 32)         /* 128 */

#define ZERO_ROW 1024u                     /* table row of zeros (pad region) */
#define TABLE_FLOATS (1024 * 27 + 32)
#define CURBUF_STRIDE 34                   /* even: aligned 64-bit stores */
#define CURBUF_FLOATS (32 * CURBUF_STRIDE)
#define CURBUF_PER_WARP (2 * CURBUF_FLOATS)
#define SMEM_FLOATS (TABLE_FLOATS + WARPS_PER_CTA * CURBUF_PER_WARP)
#define SMEM_BYTES (SMEM_FLOATS * 4) /* 180,352 B */

typedef unsigned long long u64;

__device__ __forceinline__ u64 pack2(float lo, float hi) {
    u64 r; asm("mov.b64 %0,{%1,%2};" : "=l"(r) : "f"(lo), "f"(hi)); return r;
}
__device__ __forceinline__ u64 mul2(u64 a, u64 b) {
    u64 r; asm("mul.rn.f32x2 %0,%1,%2;" : "=l"(r) : "l"(a), "l"(b)); return r;
}
__device__ __forceinline__ u64 fma2(u64 a, u64 b, u64 c) {
    u64 r; asm("fma.rn.f32x2 %0,%1,%2,%3;" : "=l"(r) : "l"(a), "l"(b), "l"(c)); return r;
}
__device__ __forceinline__ u64 add2(u64 a, u64 b) {
    u64 r; asm("add.rn.f32x2 %0,%1,%2;" : "=l"(r) : "l"(a), "l"(b)); return r;
}
// FSET: float 1.0f/0.0f from comparison, fixed-latency, no predicate.
__device__ __forceinline__ float fset_gt1(float a) {
    float r; asm("set.gt.f32.f32 %0,%1,0f3F800000;" : "=f"(r) : "f"(a)); return r;
}

// Phase A: 10 neuron currents for this lane's timestep, f32x2-packed.
// Per-half rounding == scalar ops; ascending-k order matches cublas.
__device__ __forceinline__ void phaseA_store(const float xv[6],
                                             const u64 w12r[5][6],
                                             const u64 b12r[5],
                                             float* wb, int lane)
{
    u64 xx[6];
#pragma unroll
    for (int c = 0; c < 6; c++) xx[c] = pack2(xv[c], xv[c]);
#pragma unroll
    for (int np = 0; np < 5; np++) {
        u64 a = mul2(xx[0], w12r[np][0]);
#pragma unroll
        for (int c = 1; c < 6; c++)
            a = fma2(xx[c], w12r[np][c], a);
        a = add2(a, b12r[np]);
        *reinterpret_cast<u64*>(&wb[lane * CURBUF_STRIDE + 2 * np]) = a;
    }
}

// One chunk = 4 sub-batches of 8 steps; parity p alternates (chunk-invariant).
// msk[p][i] = spike mask of global step (sb*8+i-1)  [vote lagged one step]
// c2f[p][i] = cur2 for those masks, fetched one sub-batch later
// L2 recurrence lags L1 by 17 steps; initial fakes are exact zero currents.
__device__ __forceinline__ void fused_chunk(const float* rb, int lane,
                                            const float* trow,
                                            float& m1, float& s1,
                                            float& m2, float& s2,
                                            bool& pd,
                                            unsigned (&msk)[2][8],
                                            float (&c2f)[2][8])
{
#pragma unroll
    for (int sb = 0; sb < 4; sb++) {
        const int p = sb & 1, q = p ^ 1;

        // batched c1 loads (no LDS downstream of votes on the chain)
        float c1r[8];
#pragma unroll
        for (int i = 0; i < 8; i++)
            c1r[i] = rb[(sb * 8 + i) * CURBUF_STRIDE + lane];
        // batched table fetch for previous sub-batch's masks (long drained)
#pragma unroll
        for (int i = 0; i < 8; i++)
            c2f[p][i] = trow[msk[q][i] * 27u];

#pragma unroll
        for (int i = 0; i < 8; i++) {
            // vote the PREVIOUS step's pred (>= full step old -> no stall)
            msk[p][i] = __ballot_sync(0xffffffffu, pd);

            // layer 1: mem = fma(beta,mem,cur) - s ; s = (mem>1) as float.
            // FSET keeps the predicate off the chain (reference-exact values).
            float a1 = fmaf(BETA, m1, c1r[i]);
            m1 = __fsub_rn(a1, s1);
            s1 = fset_gt1(m1);
            pd = (m1 > 1.0f);  // sink: consumed by next iteration's ballot

            // layer 2 (lagged): independent 8-cyc chain
            float a2 = fmaf(BETA, m2, c2f[q][i]);
            m2 = __fsub_rn(a2, s2);
            s2 = fset_gt1(m2);
        }
    }
}

__global__ void __launch_bounds__(CTA_THREADS, 1)
snn_kernel(const float* __restrict__ x, const float* __restrict__ W1,
           const float* __restrict__ b1, const float* __restrict__ W2,
           const float* __restrict__ b2, float* __restrict__ out)
{
    extern __shared__ float smem[];
    float* table  = smem;                 // [1024][27] + 32 zero pad (ZERO_ROW)
    float* curall = smem + TABLE_FLOATS;  // [WARPS][2][32][34]

    const int tid  = threadIdx.x;
    const int warp = tid >> 5;
    const int lane = tid & 31;
    const int b = blockIdx.x * WARPS_PER_CTA + warp;
    const float* xb = x + (size_t)b * (6 * T_LEN);

    float xv[6];
#pragma unroll
    for (int c = 0; c < 6; c++) xv[c] = xb[c * T_LEN + lane];

    // Layer-2 lookup table: ascending-n accumulation == reference fma-dot
    // with 0/1 spikes (adding 0.0f is exact).
    for (int e = tid; e < 1024 * 27; e += CTA_THREADS) {
        int v = e / 27;
        int m = e - v * 27;
        float acc = 0.0f;
#pragma unroll
        for (int n = 0; n < 10; n++)
            if (v & (1 << n)) acc = __fadd_rn(acc, W2[m * 10 + n]);
        table[e] = __fadd_rn(acc, b2[m]);
    }
    for (int i = 1024 * 27 + tid; i < TABLE_FLOATS; i += CTA_THREADS)
        table[i] = 0.0f;  // ZERO_ROW (index 1024) lives here
    // staging columns 10..31 stay zero forever -> lanes 10..31 never spike
    for (int i = tid; i < WARPS_PER_CTA * CURBUF_PER_WARP; i += CTA_THREADS)
        curall[i] = 0.0f;
    __syncthreads();

    u64 w12r[5][6], b12r[5];
#pragma unroll
    for (int np = 0; np < 5; np++) {
        b12r[np] = pack2(b1[2 * np], b1[2 * np + 1]);
#pragma unroll
        for (int c = 0; c < 6; c++)
            w12r[np][c] = pack2(W1[(2 * np) * 6 + c], W1[(2 * np + 1) * 6 + c]);
    }

    float* cbuf  = curall + warp * CURBUF_PER_WARP;
    float* bank0 = cbuf;
    float* bank1 = cbuf + CURBUF_FLOATS;
    const float* trow = table + lane;

    float m1 = 0.0f, m2 = 0.0f, s1 = 0.0f, s2 = 0.0f;
    // First ballot must yield ZERO_ROW (mask of fictitious step -1):
    // only lane 10 votes -> 1<<10 = 1024 = ZERO_ROW. Lanes 10..31 never
    // spike afterwards (their staging columns are permanently zero).
    bool pd = (lane == 10);
    unsigned msk[2][8];
    float c2f[2][8];
#pragma unroll
    for (int i = 0; i < 8; i++) {
        msk[0][i] = ZERO_ROW; msk[1][i] = ZERO_ROW;
        c2f[0][i] = 0.0f;     c2f[1][i] = 0.0f;
    }

    // Prologue: phaseA(ch0)->bank0; xv <- ch1.
    phaseA_store(xv, w12r, b12r, bank0, lane);
#pragma unroll
    for (int c = 0; c < 6; c++) xv[c] = xb[c * T_LEN + 32 + lane];
    __syncwarp();

    // Chunks 0..125 in pairs.
#pragma unroll 1
    for (int k = 0; k < 126; k += 2) {
        float xn[6];
#pragma unroll
        for (int c = 0; c < 6; c++)
            xn[c] = xb[c * T_LEN + (k + 2) * 32 + lane];
        phaseA_store(xv, w12r, b12r, bank1, lane);
        fused_chunk(bank0, lane, trow, m1, s1, m2, s2, pd, msk, c2f);
#pragma unroll
        for (int c = 0; c < 6; c++) xv[c] = xn[c];
        __syncwarp();

#pragma unroll
        for (int c = 0; c < 6; c++)
            xn[c] = xb[c * T_LEN + (k + 3) * 32 + lane];
        phaseA_store(xv, w12r, b12r, bank0, lane);
        fused_chunk(bank1, lane, trow, m1, s1, m2, s2, pd, msk, c2f);
#pragma unroll
        for (int c = 0; c < 6; c++) xv[c] = xn[c];
        __syncwarp();
    }

    // chunk 126: read bank0; phaseA(127)->bank1
    phaseA_store(xv, w12r, b12r, bank1, lane);
    fused_chunk(bank0, lane, trow, m1, s1, m2, s2, pd, msk, c2f);
    __syncwarp();
    // chunk 127: read bank1
    fused_chunk(bank1, lane, trow, m1, s1, m2, s2, pd, msk, c2f);

    // Epilogue: L2 lags by 17 steps. Last sub-batch had parity 1.
    // (1) consume c2f[1][0..7]  = cur2(steps 4079..4086)
#pragma unroll
    for (int i = 0; i < 8; i++) {
        float a2 = fmaf(BETA, m2, c2f[1][i]);
        m2 = __fsub_rn(a2, s2);
        s2 = fset_gt1(m2);
    }
    // (2) fetch+consume msk[1][0..7] = masks(steps 4087..4094)
#pragma unroll
    for (int i = 0; i < 8; i++) {
        float c = trow[msk[1][i] * 27u];
        float a2 = fmaf(BETA, m2, c);
        m2 = __fsub_rn(a2, s2);
        s2 = fset_gt1(m2);
    }
    // (3) final step 4095's mask is in pd
    {
        unsigned v = __ballot_sync(0xffffffffu, pd);
        float c = trow[v * 27u];
        float a2 = fmaf(BETA, m2, c);
        m2 = __fsub_rn(a2, s2);
        s2 = fset_gt1(m2);
    }

    if (lane < 27)
        out[b * 27 + lane] = s2;
}

extern "C" void kernel_launch(void* const* d_in, const int* in_sizes, int n_in,
                              void* d_out, int out_size)
{
    const float* x  = (const float*)d_in[0];
    const float* W1 = (const float*)d_in[1];
    const float* b1 = (const float*)d_in[2];
    const float* W2 = (const float*)d_in[3];
    const float* b2 = (const float*)d_in[4];
    float* out = (float*)d_out;

    cudaFuncSetAttribute(snn_kernel, cudaFuncAttributeMaxDynamicSharedMemorySize,
                         SMEM_BYTES);

    snn_kernel<<<N_CTAS, CTA_THREADS, SMEM_BYTES>>>(x, W1, b1, W2, b2, out);
}